// round 15
// baseline (speedup 1.0000x reference)
#include <cuda_runtime.h>
#include <cstdint>
#include <cstring>

// ---------------- constants ----------------
#define B_   128
#define C_   64
#define S_   4096
#define NROW (B_*C_)            // 8192
#define NTOT ((size_t)B_*C_*S_) // 33554432

// ---------------- scratch (no allocation allowed) ----------------
__device__ float g_sd[NROW];        // sqrt2 * 0.1 * per-row std (shared by views)
__device__ int   g_shift[2*B_];
__device__ float g_scale[2*B_];
__device__ float g_mask[2*NROW];

// ---------------- Threefry-2x32-20 (JAX-exact) ----------------
#define TF_R(x0,x1,r) { x0 += x1; x1 = __funnelshift_l(x1,x1,r); x1 ^= x0; }

// plain version (prep kernel, low volume, bit-exact)
__device__ __forceinline__ void tf_block0(uint32_t k0, uint32_t k1,
                                          uint32_t c1,
                                          uint32_t &o0, uint32_t &o1) {
  uint32_t k2 = k0 ^ k1 ^ 0x1BD11BDAu;
  uint32_t x0 = k0, x1 = c1 + k1;
  TF_R(x0,x1,13) TF_R(x0,x1,15) TF_R(x0,x1,26) TF_R(x0,x1,6)
  x0 += k1; x1 += k2 + 1u;
  TF_R(x0,x1,17) TF_R(x0,x1,29) TF_R(x0,x1,16) TF_R(x0,x1,24)
  x0 += k2; x1 += k0 + 2u;
  TF_R(x0,x1,13) TF_R(x0,x1,15) TF_R(x0,x1,26) TF_R(x0,x1,6)
  x0 += k0; x1 += k1 + 3u;
  TF_R(x0,x1,17) TF_R(x0,x1,29) TF_R(x0,x1,16) TF_R(x0,x1,24)
  x0 += k1; x1 += k2 + 4u;
  TF_R(x0,x1,13) TF_R(x0,x1,15) TF_R(x0,x1,26) TF_R(x0,x1,6)
  o0 = x0 + k2; o1 = x1 + k0 + 5u;
}

__device__ __forceinline__ uint32_t xbits(uint32_t k0, uint32_t k1, uint32_t i) {
  uint32_t o0, o1;
  tf_block0(k0, k1, i, o0, o1);
  return o0 ^ o1;
}

// ---- hot-path block: EVERY add as IMAD (fma pipe) via runtime `one`.
// alu keeps only the structural SHF+LOP3 floor. Key-derived constants from params.
#define MAD1(d,a) asm("mad.lo.u32 %0, %1, %2, %0;" : "+r"(d) : "r"(a), "r"(one))
#define TF_RM(r)  { MAD1(x0,x1); x1 = __funnelshift_l(x1,x1,r); x1 ^= x0; }

// kk = (k0, k1, k2, i1); ii = (i2, i3, i4, i5)
__device__ __forceinline__ uint32_t tf_xor(const uint4 kk, const uint4 ii,
                                           uint32_t x1init, uint32_t one) {
  uint32_t x0 = kk.x, x1 = x1init;
  TF_RM(13) TF_RM(15) TF_RM(26) TF_RM(6)
  MAD1(x0, kk.y); MAD1(x1, kk.w);
  TF_RM(17) TF_RM(29) TF_RM(16) TF_RM(24)
  MAD1(x0, kk.z); MAD1(x1, ii.x);
  TF_RM(13) TF_RM(15) TF_RM(26) TF_RM(6)
  MAD1(x0, kk.x); MAD1(x1, ii.y);
  TF_RM(17) TF_RM(29) TF_RM(16) TF_RM(24)
  MAD1(x0, kk.y); MAD1(x1, ii.z);
  TF_RM(13) TF_RM(15) TF_RM(26) TF_RM(6)
  MAD1(x0, kk.z); MAD1(x1, ii.w);
  return (x0 ^ x1) | 0x200u;
}

// bits -> float in [0,1): JAX _uniform exact (prep path)
__device__ __forceinline__ float u01(uint32_t b) {
  return __uint_as_float((b >> 9) | 0x3F800000u) - 1.0f;
}

// ---------------- packed f32x2 helpers ----------------
#define FMA2(d,a,b,c) asm("fma.rn.f32x2 %0, %1, %2, %3;" : "=l"(d) : "l"(a), "l"(b), "l"(c))
#define MUL2(d,a,b)   asm("mul.rn.f32x2 %0, %1, %2;"     : "=l"(d) : "l"(a), "l"(b))

__device__ __forceinline__ uint64_t pk2(float lo, float hi) {
  uint64_t r; asm("mov.b64 %0, {%1, %2};" : "=l"(r) : "f"(lo), "f"(hi)); return r;
}

// rare tail branch (w >= 5; ~0.34% of draws)
__device__ __forceinline__ float erfinv_tail(float v) {
  float w = -0.69314718f * v;
  float t = sqrtf(w) - 3.0f;
  float p = 0.00573950773f;
  p = fmaf(p, t, -0.0076224613f);
  p = fmaf(p, t, 0.00943887047f);
  p = fmaf(p, t, 1.00167406f);
  p = fmaf(p, t, 2.83297682f);
  return p;
}

// erfinv for the two views of one element, central poly packed f32x2.
// Lane-wise IEEE-identical to the scalar version (validated: rel_err match).
// Packed coefficients come from kernel params.
__device__ __forceinline__ void erfinv_pair(uint32_t ba, uint32_t bb,
                                            uint64_t c0, uint64_t c1,
                                            uint64_t c2, uint64_t c3,
                                            uint64_t c4,
                                            float &za, float &zb) {
  uint32_t ia, ib;
  asm("mad.hi.u32 %0, %1, 0x800000U, 0x40000000U;" : "=r"(ia) : "r"(ba));
  asm("mad.hi.u32 %0, %1, 0x800000U, 0x40000000U;" : "=r"(ib) : "r"(bb));
  float xa = __uint_as_float(ia) - 3.0f;        // in (-1,1), never +-1
  float xb = __uint_as_float(ib) - 3.0f;
  float va = __log2f(fmaf(-xa, xa, 1.0f));      // lg2(1 - x^2) < 0
  float vb = __log2f(fmaf(-xb, xb, 1.0f));
  uint64_t vv = pk2(va, vb);
  uint64_t xx = pk2(xa, xb);
  uint64_t pp = c0;
  FMA2(pp, pp, vv, c1);
  FMA2(pp, pp, vv, c2);
  FMA2(pp, pp, vv, c3);
  FMA2(pp, pp, vv, c4);
  uint64_t zz;
  MUL2(zz, pp, xx);
  asm("mov.b64 {%0, %1}, %2;" : "=f"(za), "=f"(zb) : "l"(zz));
  if (va <= -7.2134752f) za = erfinv_tail(va) * xa;   // w >= 5 tail fixup
  if (vb <= -7.2134752f) zb = erfinv_tail(vb) * xb;
}

// ---------------- fused prep: per-row std + shifts/masks/scales ----------------
__global__ void prep_kernel(const float* __restrict__ x,
                            uint4 kshA, uint4 kshB, uint4 kmask, uint4 kscale) {
  unsigned gt = blockIdx.x * blockDim.x + threadIdx.x;
  if (gt < 2u * 8448u) {
    int v = (gt >= 8448u);
    unsigned i = gt - (unsigned)v * 8448u;
    if (i < 8192u) {
      uint32_t k0 = v ? kmask.z : kmask.x, k1 = v ? kmask.w : kmask.y;
      g_mask[v * NROW + i] = (u01(xbits(k0, k1, i)) > 0.1f) ? 1.0f : 0.0f;
    } else if (i < 8320u) {
      // randint: k1,k2 = split(k_shift); higher from k1, lower from k2; 68 = 2^32 % 101
      unsigned b = i - 8192u;
      uint4 ks = v ? kshB : kshA;
      uint32_t hb = xbits(ks.x, ks.y, b);
      uint32_t lb = xbits(ks.z, ks.w, b);
      uint32_t off = ((hb % 101u) * 68u + (lb % 101u)) % 101u;
      g_shift[v * B_ + b] = -50 + (int)off;
    } else {
      unsigned j = i - 8320u;
      uint32_t k0 = v ? kscale.z : kscale.x, k1 = v ? kscale.w : kscale.y;
      float u = u01(xbits(k0, k1, j));
      const float span = 1.2f - 0.8f;
      g_scale[v * B_ + j] = fmaxf(0.8f, __fadd_rn(__fmul_rn(u, span), 0.8f));
    }
  }

  int row = blockIdx.x;
  const float4* xr = reinterpret_cast<const float4*>(x + ((size_t)row << 12));
  float s = 0.0f, q = 0.0f;
#pragma unroll
  for (int i = 0; i < 8; i++) {
    float4 v = xr[threadIdx.x + (i << 7)];
    s += (v.x + v.y) + (v.z + v.w);
    q += (v.x * v.x + v.y * v.y) + (v.z * v.z + v.w * v.w);
  }
#pragma unroll
  for (int o = 16; o; o >>= 1) {
    s += __shfl_down_sync(0xFFFFFFFFu, s, o);
    q += __shfl_down_sync(0xFFFFFFFFu, q, o);
  }
  __shared__ float ss[4], qq[4];
  int w = threadIdx.x >> 5;
  if ((threadIdx.x & 31) == 0) { ss[w] = s; qq[w] = q; }
  __syncthreads();
  if (threadIdx.x == 0) {
    s = ss[0] + ss[1] + ss[2] + ss[3];
    q = qq[0] + qq[1] + qq[2] + qq[3];
    float mean = s * (1.0f / 4096.0f);
    float var = (q - 4096.0f * mean * mean) * (1.0f / 4095.0f);
    // fold 0.1 (NOISE_STD) and sqrt(2) (from normal) into one factor
    g_sd[row] = 0.141421356237f * sqrtf(fmaxf(var, 0.0f));
  }
}

// ---------------- main: 8 consecutive elements per thread, both views ----------------
// Fast path: roll window wrap-free for this thread -> direct LDG with immediate
// offsets (no per-load AND/ADD). Slow path (~0.4% of threads): masked indexing.
#define MAIN_BODY(LOAD0, LOAD1)                                              \
  _Pragma("unroll")                                                          \
  for (int g = 0; g < 2; g++) {                                              \
    float4 o0v, o1v;                                                         \
    float* p0 = &o0v.x;                                                      \
    float* p1 = &o1v.x;                                                      \
    _Pragma("unroll")                                                        \
    for (int j = 0; j < 4; j++) {                                            \
      unsigned e = 4u * g + j;                                               \
      uint32_t wa = tf_xor(kA, iA, tka + e, one);                            \
      uint32_t wb = tf_xor(kB, iB, tkb + e, one);                            \
      float z0, z1;                                                          \
      erfinv_pair(wa, wb, c0, c1, c2, c3, c4, z0, z1);                       \
      float xv0 = (LOAD0);                                                   \
      float xv1 = (LOAD1);                                                   \
      p0[j] = (xv0 + z0 * sd) * ms0;                                         \
      p1[j] = (xv1 + z1 * sd) * ms1;                                         \
    }                                                                        \
    *reinterpret_cast<float4*>(out + base + s0 + 4u * g)        = o0v;       \
    *reinterpret_cast<float4*>(out + NTOT + base + s0 + 4u * g) = o1v;       \
  }

__global__ void __launch_bounds__(256) main_kernel(const float* __restrict__ x,
                                                   float* __restrict__ out,
                                                   uint4 kA, uint4 iA,
                                                   uint4 kB, uint4 iB,
                                                   uint64_t c0, uint64_t c1,
                                                   uint64_t c2, uint64_t c3,
                                                   uint64_t c4,
                                                   uint32_t one) {
  unsigned t0 = (blockIdx.x * blockDim.x + threadIdx.x) * 8u;  // s%8==0
  int b = t0 >> 18;
  int s0 = t0 & 4095;
  int row = t0 >> 12;
  size_t base = (size_t)row << 12;
  float sd = g_sd[row];
  unsigned u0 = (unsigned)((s0 - g_shift[b]) & 4095);        // rolled start, view 0
  unsigned u1 = (unsigned)((s0 - g_shift[B_ + b]) & 4095);   // rolled start, view 1
  float ms0 = g_mask[row]        * g_scale[b];
  float ms1 = g_mask[NROW + row] * g_scale[B_ + b];
  const float* xb = x + base;

  uint32_t tka = t0 + kA.y;   // counter + k1, view 0
  uint32_t tkb = t0 + kB.y;   // counter + k1, view 1

  if (u0 <= 4088u && u1 <= 4088u) {            // wrap-free (99.6% of threads)
    const float* pa = xb + u0;
    const float* pb = xb + u1;
    MAIN_BODY(__ldg(pa + e), __ldg(pb + e))
  } else {                                     // wrapping window
    MAIN_BODY(__ldg(xb + ((u0 + e) & 4095u)), __ldg(xb + ((u1 + e) & 4095u)))
  }
}

// ---------------- host-side Threefry for constant key derivation ----------------
static inline uint32_t h_rotl(uint32_t x, int r) { return (x << r) | (x >> (32 - r)); }
static void h_tf(uint32_t k0, uint32_t k1, uint32_t x0, uint32_t x1,
                 uint32_t* o0, uint32_t* o1) {
  uint32_t k2 = k0 ^ k1 ^ 0x1BD11BDAu;
  x0 += k0; x1 += k1;
#define HR(r) { x0 += x1; x1 = h_rotl(x1, r); x1 ^= x0; }
  HR(13) HR(15) HR(26) HR(6)  x0 += k1; x1 += k2 + 1u;
  HR(17) HR(29) HR(16) HR(24) x0 += k2; x1 += k0 + 2u;
  HR(13) HR(15) HR(26) HR(6)  x0 += k0; x1 += k1 + 3u;
  HR(17) HR(29) HR(16) HR(24) x0 += k1; x1 += k2 + 4u;
  HR(13) HR(15) HR(26) HR(6)  x0 += k2; x1 += k0 + 5u;
#undef HR
  *o0 = x0; *o1 = x1;
}

static inline uint64_t h_pk2(float f) {
  uint32_t b; memcpy(&b, &f, 4);
  return (uint64_t)b | ((uint64_t)b << 32);
}

extern "C" void kernel_launch(void* const* d_in, const int* in_sizes, int n_in,
                              void* d_out, int out_size) {
  const float* x = (const float*)d_in[0];
  float* out = (float*)d_out;

  uint32_t vk[2][2];
  h_tf(0u, 42u, 0u, 1u, &vk[0][0], &vk[0][1]);
  h_tf(0u, 42u, 0u, 2u, &vk[1][0], &vk[1][1]);

  uint4 kshA, kshB, kmask, kscale;
  uint32_t kn[2][2];   // noise keys per view
  for (int v = 0; v < 2; v++) {
    uint32_t kj[4][2];
    for (uint32_t j = 0; j < 4; j++)
      h_tf(vk[v][0], vk[v][1], 0u, j, &kj[j][0], &kj[j][1]);
    uint32_t s1[2], s2[2];
    h_tf(kj[0][0], kj[0][1], 0u, 0u, &s1[0], &s1[1]);
    h_tf(kj[0][0], kj[0][1], 0u, 1u, &s2[0], &s2[1]);
    kn[v][0] = kj[1][0]; kn[v][1] = kj[1][1];
    if (v == 0) {
      kshA.x = s1[0]; kshA.y = s1[1]; kshA.z = s2[0]; kshA.w = s2[1];
      kmask.x  = kj[2][0]; kmask.y  = kj[2][1];
      kscale.x = kj[3][0]; kscale.y = kj[3][1];
    } else {
      kshB.x = s1[0]; kshB.y = s1[1]; kshB.z = s2[0]; kshB.w = s2[1];
      kmask.z  = kj[2][0]; kmask.w  = kj[2][1];
      kscale.z = kj[3][0]; kscale.w = kj[3][1];
    }
  }

  // derived threefry constants, host-side (live in param/constant space)
  uint4 kkv[2], iiv[2];
  for (int v = 0; v < 2; v++) {
    uint32_t k0 = kn[v][0], k1 = kn[v][1];
    uint32_t k2 = k0 ^ k1 ^ 0x1BD11BDAu;
    kkv[v].x = k0;      kkv[v].y = k1;      kkv[v].z = k2;      kkv[v].w = k2 + 1u;
    iiv[v].x = k0 + 2u; iiv[v].y = k1 + 3u; iiv[v].z = k2 + 4u; iiv[v].w = k0 + 5u;
  }

  // packed erfinv central-poly coefficients (v-space)
  uint64_t c0 = h_pk2(5.0456135e-5f);
  uint64_t c1 = h_pk2(1.1454495e-3f);
  uint64_t c2 = h_pk2(6.4486591e-3f);
  uint64_t c3 = h_pk2(-0.15967367f);
  uint64_t c4 = h_pk2(0.88682485f);

  prep_kernel<<<NROW, 128>>>(x, kshA, kshB, kmask, kscale);
  main_kernel<<<(unsigned)(NTOT / 8 / 256), 256>>>(x, out, kkv[0], iiv[0],
                                                   kkv[1], iiv[1],
                                                   c0, c1, c2, c3, c4, 1u);
}

// round 16
// speedup vs baseline: 1.2719x; 1.2719x over previous
#include <cuda_runtime.h>
#include <cstdint>

// ---------------- constants ----------------
#define B_   128
#define C_   64
#define S_   4096
#define NROW (B_*C_)            // 8192
#define NTOT ((size_t)B_*C_*S_) // 33554432

// ---------------- scratch (no allocation allowed) ----------------
__device__ float g_sd[NROW];        // sqrt2 * 0.1 * per-row std (shared by views)
__device__ int   g_shift[2*B_];
__device__ float g_scale[2*B_];
__device__ float g_mask[2*NROW];

// ---------------- Threefry-2x32-20 (JAX-exact) ----------------
#define TF_R(x0,x1,r) { x0 += x1; x1 = __funnelshift_l(x1,x1,r); x1 ^= x0; }

// plain version (prep kernel, low volume, bit-exact)
__device__ __forceinline__ void tf_block0(uint32_t k0, uint32_t k1,
                                          uint32_t c1,
                                          uint32_t &o0, uint32_t &o1) {
  uint32_t k2 = k0 ^ k1 ^ 0x1BD11BDAu;
  uint32_t x0 = k0, x1 = c1 + k1;
  TF_R(x0,x1,13) TF_R(x0,x1,15) TF_R(x0,x1,26) TF_R(x0,x1,6)
  x0 += k1; x1 += k2 + 1u;
  TF_R(x0,x1,17) TF_R(x0,x1,29) TF_R(x0,x1,16) TF_R(x0,x1,24)
  x0 += k2; x1 += k0 + 2u;
  TF_R(x0,x1,13) TF_R(x0,x1,15) TF_R(x0,x1,26) TF_R(x0,x1,6)
  x0 += k0; x1 += k1 + 3u;
  TF_R(x0,x1,17) TF_R(x0,x1,29) TF_R(x0,x1,16) TF_R(x0,x1,24)
  x0 += k1; x1 += k2 + 4u;
  TF_R(x0,x1,13) TF_R(x0,x1,15) TF_R(x0,x1,26) TF_R(x0,x1,6)
  o0 = x0 + k2; o1 = x1 + k0 + 5u;
}

__device__ __forceinline__ uint32_t xbits(uint32_t k0, uint32_t k1, uint32_t i) {
  uint32_t o0, o1;
  tf_block0(k0, k1, i, o0, o1);
  return o0 ^ o1;
}

// ---- hot-path block: EVERY add as IMAD (fma pipe) via runtime `one`.
// alu keeps only the structural SHF+LOP3 floor. Key-derived constants come
// from kernel params (UR path on sm_103a) — zero GPR cost.
// Output: (x0^x1)|0x200 — forces the uniform's low mantissa bit so x != -1.
#define MAD1(d,a) asm("mad.lo.u32 %0, %1, %2, %0;" : "+r"(d) : "r"(a), "r"(one))
#define TF_RM(r)  { MAD1(x0,x1); x1 = __funnelshift_l(x1,x1,r); x1 ^= x0; }

// kk = (k0, k1, k2, i1); ii = (i2, i3, i4, i5)
__device__ __forceinline__ uint32_t tf_xor(const uint4 kk, const uint4 ii,
                                           uint32_t x1init, uint32_t one) {
  uint32_t x0 = kk.x, x1 = x1init;
  TF_RM(13) TF_RM(15) TF_RM(26) TF_RM(6)
  MAD1(x0, kk.y); MAD1(x1, kk.w);
  TF_RM(17) TF_RM(29) TF_RM(16) TF_RM(24)
  MAD1(x0, kk.z); MAD1(x1, ii.x);
  TF_RM(13) TF_RM(15) TF_RM(26) TF_RM(6)
  MAD1(x0, kk.x); MAD1(x1, ii.y);
  TF_RM(17) TF_RM(29) TF_RM(16) TF_RM(24)
  MAD1(x0, kk.y); MAD1(x1, ii.z);
  TF_RM(13) TF_RM(15) TF_RM(26) TF_RM(6)
  MAD1(x0, kk.z); MAD1(x1, ii.w);
  return (x0 ^ x1) | 0x200u;
}

// bits -> float in [0,1): JAX _uniform exact (prep path)
__device__ __forceinline__ float u01(uint32_t b) {
  return __uint_as_float((b >> 9) | 0x3F800000u) - 1.0f;
}

// ---------------- packed f32x2 helpers ----------------
__device__ __forceinline__ uint64_t pk2(float lo, float hi) {
  uint64_t r; asm("mov.b64 %0, {%1, %2};" : "=l"(r) : "f"(lo), "f"(hi)); return r;
}
#define FMA2(d,a,b,c) asm("fma.rn.f32x2 %0, %1, %2, %3;" : "=l"(d) : "l"(a), "l"(b), "l"(c))
#define MUL2(d,a,b)   asm("mul.rn.f32x2 %0, %1, %2;"     : "=l"(d) : "l"(a), "l"(b))

// rare tail branch (w >= 5; ~0.34% of draws)
__device__ __forceinline__ float erfinv_tail(float v) {
  float w = -0.69314718f * v;
  float t = sqrtf(w) - 3.0f;
  float p = 0.00573950773f;
  p = fmaf(p, t, -0.0076224613f);
  p = fmaf(p, t, 0.00943887047f);
  p = fmaf(p, t, 1.00167406f);
  p = fmaf(p, t, 2.83297682f);
  return p;
}

// erfinv for the two views of one element, central poly packed f32x2.
// Lane-wise IEEE-identical to the scalar version (validated: rel_err match).
__device__ __forceinline__ void erfinv_pair(uint32_t ba, uint32_t bb,
                                            float &za, float &zb) {
  uint32_t ia, ib;
  asm("mad.hi.u32 %0, %1, 0x800000U, 0x40000000U;" : "=r"(ia) : "r"(ba));
  asm("mad.hi.u32 %0, %1, 0x800000U, 0x40000000U;" : "=r"(ib) : "r"(bb));
  float xa = __uint_as_float(ia) - 3.0f;        // in (-1,1), never +-1
  float xb = __uint_as_float(ib) - 3.0f;
  float va = __log2f(fmaf(-xa, xa, 1.0f));      // lg2(1 - x^2) < 0
  float vb = __log2f(fmaf(-xb, xb, 1.0f));
  uint64_t vv = pk2(va, vb);
  uint64_t xx = pk2(xa, xb);
  uint64_t pp = pk2(5.0456135e-5f, 5.0456135e-5f);
  const uint64_t c1 = pk2(1.1454495e-3f, 1.1454495e-3f);
  const uint64_t c2 = pk2(6.4486591e-3f, 6.4486591e-3f);
  const uint64_t c3 = pk2(-0.15967367f, -0.15967367f);
  const uint64_t c4 = pk2(0.88682485f, 0.88682485f);
  FMA2(pp, pp, vv, c1);
  FMA2(pp, pp, vv, c2);
  FMA2(pp, pp, vv, c3);
  FMA2(pp, pp, vv, c4);
  uint64_t zz;
  MUL2(zz, pp, xx);
  asm("mov.b64 {%0, %1}, %2;" : "=f"(za), "=f"(zb) : "l"(zz));
  if (va <= -7.2134752f) za = erfinv_tail(va) * xa;   // w >= 5 tail fixup
  if (vb <= -7.2134752f) zb = erfinv_tail(vb) * xb;
}

// ---------------- fused prep: per-row std + shifts/masks/scales ----------------
__global__ void prep_kernel(const float* __restrict__ x,
                            uint4 kshA, uint4 kshB, uint4 kmask, uint4 kscale) {
  unsigned gt = blockIdx.x * blockDim.x + threadIdx.x;
  if (gt < 2u * 8448u) {
    int v = (gt >= 8448u);
    unsigned i = gt - (unsigned)v * 8448u;
    if (i < 8192u) {
      uint32_t k0 = v ? kmask.z : kmask.x, k1 = v ? kmask.w : kmask.y;
      g_mask[v * NROW + i] = (u01(xbits(k0, k1, i)) > 0.1f) ? 1.0f : 0.0f;
    } else if (i < 8320u) {
      // randint: k1,k2 = split(k_shift); higher from k1, lower from k2; 68 = 2^32 % 101
      unsigned b = i - 8192u;
      uint4 ks = v ? kshB : kshA;
      uint32_t hb = xbits(ks.x, ks.y, b);
      uint32_t lb = xbits(ks.z, ks.w, b);
      uint32_t off = ((hb % 101u) * 68u + (lb % 101u)) % 101u;
      g_shift[v * B_ + b] = -50 + (int)off;
    } else {
      unsigned j = i - 8320u;
      uint32_t k0 = v ? kscale.z : kscale.x, k1 = v ? kscale.w : kscale.y;
      float u = u01(xbits(k0, k1, j));
      const float span = 1.2f - 0.8f;
      g_scale[v * B_ + j] = fmaxf(0.8f, __fadd_rn(__fmul_rn(u, span), 0.8f));
    }
  }

  int row = blockIdx.x;
  const float4* xr = reinterpret_cast<const float4*>(x + ((size_t)row << 12));
  float s = 0.0f, q = 0.0f;
#pragma unroll
  for (int i = 0; i < 8; i++) {
    float4 v = xr[threadIdx.x + (i << 7)];
    s += (v.x + v.y) + (v.z + v.w);
    q += (v.x * v.x + v.y * v.y) + (v.z * v.z + v.w * v.w);
  }
#pragma unroll
  for (int o = 16; o; o >>= 1) {
    s += __shfl_down_sync(0xFFFFFFFFu, s, o);
    q += __shfl_down_sync(0xFFFFFFFFu, q, o);
  }
  __shared__ float ss[4], qq[4];
  int w = threadIdx.x >> 5;
  if ((threadIdx.x & 31) == 0) { ss[w] = s; qq[w] = q; }
  __syncthreads();
  if (threadIdx.x == 0) {
    s = ss[0] + ss[1] + ss[2] + ss[3];
    q = qq[0] + qq[1] + qq[2] + qq[3];
    float mean = s * (1.0f / 4096.0f);
    float var = (q - 4096.0f * mean * mean) * (1.0f / 4095.0f);
    // fold 0.1 (NOISE_STD) and sqrt(2) (from normal) into one factor
    g_sd[row] = 0.141421356237f * sqrtf(fmaxf(var, 0.0f));
  }
}

// ---------------- main: 8 consecutive elements per thread, both views ----------------
// kA = (ka0, ka1, ka2, ka2+1); iA = (ka0+2, ka1+3, ka2+4, ka0+5); same for B.
__global__ void __launch_bounds__(256) main_kernel(const float* __restrict__ x,
                                                   float* __restrict__ out,
                                                   uint4 kA, uint4 iA,
                                                   uint4 kB, uint4 iB,
                                                   uint32_t one) {
  unsigned t0 = (blockIdx.x * blockDim.x + threadIdx.x) * 8u;  // s%8==0
  int b = t0 >> 18;
  int s0 = t0 & 4095;
  int row = t0 >> 12;
  size_t base = (size_t)row << 12;
  float sd = g_sd[row];
  unsigned u0 = (unsigned)((s0 - g_shift[b]) & 4095);        // rolled start, view 0
  unsigned u1 = (unsigned)((s0 - g_shift[B_ + b]) & 4095);   // rolled start, view 1
  float ms0 = g_mask[row]        * g_scale[b];
  float ms1 = g_mask[NROW + row] * g_scale[B_ + b];
  const float* xb = x + base;

  uint32_t tka = t0 + kA.y;   // counter + k1, view 0
  uint32_t tkb = t0 + kB.y;   // counter + k1, view 1

#pragma unroll
  for (int g = 0; g < 2; g++) {                 // two float4 groups
    float4 o0, o1;
    float* p0 = &o0.x;
    float* p1 = &o1.x;
#pragma unroll
    for (int j = 0; j < 4; j++) {
      unsigned e = 4u * g + j;
      uint32_t wa = tf_xor(kA, iA, tka + e, one);
      uint32_t wb = tf_xor(kB, iB, tkb + e, one);
      float z0, z1;
      erfinv_pair(wa, wb, z0, z1);
      float xv0 = __ldg(xb + ((u0 + e) & 4095u));
      float xv1 = __ldg(xb + ((u1 + e) & 4095u));
      p0[j] = (xv0 + z0 * sd) * ms0;
      p1[j] = (xv1 + z1 * sd) * ms1;
    }
    *reinterpret_cast<float4*>(out + base + s0 + 4u * g)        = o0;
    *reinterpret_cast<float4*>(out + NTOT + base + s0 + 4u * g) = o1;
  }
}

// ---------------- host-side Threefry for constant key derivation ----------------
static inline uint32_t h_rotl(uint32_t x, int r) { return (x << r) | (x >> (32 - r)); }
static void h_tf(uint32_t k0, uint32_t k1, uint32_t x0, uint32_t x1,
                 uint32_t* o0, uint32_t* o1) {
  uint32_t k2 = k0 ^ k1 ^ 0x1BD11BDAu;
  x0 += k0; x1 += k1;
#define HR(r) { x0 += x1; x1 = h_rotl(x1, r); x1 ^= x0; }
  HR(13) HR(15) HR(26) HR(6)  x0 += k1; x1 += k2 + 1u;
  HR(17) HR(29) HR(16) HR(24) x0 += k2; x1 += k0 + 2u;
  HR(13) HR(15) HR(26) HR(6)  x0 += k0; x1 += k1 + 3u;
  HR(17) HR(29) HR(16) HR(24) x0 += k1; x1 += k2 + 4u;
  HR(13) HR(15) HR(26) HR(6)  x0 += k2; x1 += k0 + 5u;
#undef HR
  *o0 = x0; *o1 = x1;
}

extern "C" void kernel_launch(void* const* d_in, const int* in_sizes, int n_in,
                              void* d_out, int out_size) {
  const float* x = (const float*)d_in[0];
  float* out = (float*)d_out;

  uint32_t vk[2][2];
  h_tf(0u, 42u, 0u, 1u, &vk[0][0], &vk[0][1]);
  h_tf(0u, 42u, 0u, 2u, &vk[1][0], &vk[1][1]);

  uint4 kshA, kshB, kmask, kscale;
  uint32_t kn[2][2];   // noise keys per view
  for (int v = 0; v < 2; v++) {
    uint32_t kj[4][2];
    for (uint32_t j = 0; j < 4; j++)
      h_tf(vk[v][0], vk[v][1], 0u, j, &kj[j][0], &kj[j][1]);
    uint32_t s1[2], s2[2];
    h_tf(kj[0][0], kj[0][1], 0u, 0u, &s1[0], &s1[1]);
    h_tf(kj[0][0], kj[0][1], 0u, 1u, &s2[0], &s2[1]);
    kn[v][0] = kj[1][0]; kn[v][1] = kj[1][1];
    if (v == 0) {
      kshA.x = s1[0]; kshA.y = s1[1]; kshA.z = s2[0]; kshA.w = s2[1];
      kmask.x  = kj[2][0]; kmask.y  = kj[2][1];
      kscale.x = kj[3][0]; kscale.y = kj[3][1];
    } else {
      kshB.x = s1[0]; kshB.y = s1[1]; kshB.z = s2[0]; kshB.w = s2[1];
      kmask.z  = kj[2][0]; kmask.w  = kj[2][1];
      kscale.z = kj[3][0]; kscale.w = kj[3][1];
    }
  }

  // derived threefry constants, host-side (live in param/constant space)
  uint4 kkv[2], iiv[2];
  for (int v = 0; v < 2; v++) {
    uint32_t k0 = kn[v][0], k1 = kn[v][1];
    uint32_t k2 = k0 ^ k1 ^ 0x1BD11BDAu;
    kkv[v].x = k0;      kkv[v].y = k1;      kkv[v].z = k2;      kkv[v].w = k2 + 1u;
    iiv[v].x = k0 + 2u; iiv[v].y = k1 + 3u; iiv[v].z = k2 + 4u; iiv[v].w = k0 + 5u;
  }

  prep_kernel<<<NROW, 128>>>(x, kshA, kshB, kmask, kscale);
  main_kernel<<<(unsigned)(NTOT / 8 / 256), 256>>>(x, out, kkv[0], iiv[0],
                                                   kkv[1], iiv[1], 1u);
}

// round 17
// speedup vs baseline: 1.3874x; 1.0908x over previous
#include <cuda_runtime.h>
#include <cstdint>

// ---------------- constants ----------------
#define B_   128
#define C_   64
#define S_   4096
#define NROW (B_*C_)            // 8192
#define NTOT ((size_t)B_*C_*S_) // 33554432

// ---------------- Threefry-2x32-20 (JAX-exact) ----------------
#define TF_R(x0,x1,r) { x0 += x1; x1 = __funnelshift_l(x1,x1,r); x1 ^= x0; }

// generic block, counter (0, c1) — used for per-row constants (low volume)
__device__ __forceinline__ uint32_t xbits(uint32_t k0, uint32_t k1, uint32_t c1) {
  uint32_t k2 = k0 ^ k1 ^ 0x1BD11BDAu;
  uint32_t x0 = k0, x1 = c1 + k1;
  TF_R(x0,x1,13) TF_R(x0,x1,15) TF_R(x0,x1,26) TF_R(x0,x1,6)
  x0 += k1; x1 += k2 + 1u;
  TF_R(x0,x1,17) TF_R(x0,x1,29) TF_R(x0,x1,16) TF_R(x0,x1,24)
  x0 += k2; x1 += k0 + 2u;
  TF_R(x0,x1,13) TF_R(x0,x1,15) TF_R(x0,x1,26) TF_R(x0,x1,6)
  x0 += k0; x1 += k1 + 3u;
  TF_R(x0,x1,17) TF_R(x0,x1,29) TF_R(x0,x1,16) TF_R(x0,x1,24)
  x0 += k1; x1 += k2 + 4u;
  TF_R(x0,x1,13) TF_R(x0,x1,15) TF_R(x0,x1,26) TF_R(x0,x1,6)
  return (x0 + k2) ^ (x1 + k0 + 5u);
}

// ---- hot-path block: EVERY add as IMAD (fma pipe) via runtime `one`.
// alu keeps only the structural SHF+LOP3 floor.
// Output: (x0^x1)|0x200 — forces the uniform's low mantissa bit so x != -1.
#define MAD1(d,a) asm("mad.lo.u32 %0, %1, %2, %0;" : "+r"(d) : "r"(a), "r"(one))
#define TF_RM(r)  { MAD1(x0,x1); x1 = __funnelshift_l(x1,x1,r); x1 ^= x0; }

// kk = (k0, k1, k2, i1); ii = (i2, i3, i4, i5)
__device__ __forceinline__ uint32_t tf_xor(const uint4 kk, const uint4 ii,
                                           uint32_t x1init, uint32_t one) {
  uint32_t x0 = kk.x, x1 = x1init;
  TF_RM(13) TF_RM(15) TF_RM(26) TF_RM(6)
  MAD1(x0, kk.y); MAD1(x1, kk.w);
  TF_RM(17) TF_RM(29) TF_RM(16) TF_RM(24)
  MAD1(x0, kk.z); MAD1(x1, ii.x);
  TF_RM(13) TF_RM(15) TF_RM(26) TF_RM(6)
  MAD1(x0, kk.x); MAD1(x1, ii.y);
  TF_RM(17) TF_RM(29) TF_RM(16) TF_RM(24)
  MAD1(x0, kk.y); MAD1(x1, ii.z);
  TF_RM(13) TF_RM(15) TF_RM(26) TF_RM(6)
  MAD1(x0, kk.z); MAD1(x1, ii.w);
  return (x0 ^ x1) | 0x200u;
}

// bits -> float in [0,1): JAX _uniform exact (constants path)
__device__ __forceinline__ float u01(uint32_t b) {
  return __uint_as_float((b >> 9) | 0x3F800000u) - 1.0f;
}

// ---------------- packed f32x2 helpers ----------------
__device__ __forceinline__ uint64_t pk2(float lo, float hi) {
  uint64_t r; asm("mov.b64 %0, {%1, %2};" : "=l"(r) : "f"(lo), "f"(hi)); return r;
}
#define FMA2(d,a,b,c) asm("fma.rn.f32x2 %0, %1, %2, %3;" : "=l"(d) : "l"(a), "l"(b), "l"(c))
#define MUL2(d,a,b)   asm("mul.rn.f32x2 %0, %1, %2;"     : "=l"(d) : "l"(a), "l"(b))

// rare tail branch (w >= 5; ~0.34% of draws)
__device__ __forceinline__ float erfinv_tail(float v) {
  float w = -0.69314718f * v;
  float t = sqrtf(w) - 3.0f;
  float p = 0.00573950773f;
  p = fmaf(p, t, -0.0076224613f);
  p = fmaf(p, t, 0.00943887047f);
  p = fmaf(p, t, 1.00167406f);
  p = fmaf(p, t, 2.83297682f);
  return p;
}

// erfinv (sans sqrt2; folded into sd) for the two views of one element,
// central poly packed f32x2. Lane-wise IEEE-identical to scalar (validated).
__device__ __forceinline__ void erfinv_pair(uint32_t ba, uint32_t bb,
                                            float &za, float &zb) {
  uint32_t ia, ib;
  asm("mad.hi.u32 %0, %1, 0x800000U, 0x40000000U;" : "=r"(ia) : "r"(ba));
  asm("mad.hi.u32 %0, %1, 0x800000U, 0x40000000U;" : "=r"(ib) : "r"(bb));
  float xa = __uint_as_float(ia) - 3.0f;        // in (-1,1), never +-1
  float xb = __uint_as_float(ib) - 3.0f;
  float va = __log2f(fmaf(-xa, xa, 1.0f));      // lg2(1 - x^2) < 0
  float vb = __log2f(fmaf(-xb, xb, 1.0f));
  uint64_t vv = pk2(va, vb);
  uint64_t xx = pk2(xa, xb);
  uint64_t pp = pk2(5.0456135e-5f, 5.0456135e-5f);
  const uint64_t c1 = pk2(1.1454495e-3f, 1.1454495e-3f);
  const uint64_t c2 = pk2(6.4486591e-3f, 6.4486591e-3f);
  const uint64_t c3 = pk2(-0.15967367f, -0.15967367f);
  const uint64_t c4 = pk2(0.88682485f, 0.88682485f);
  FMA2(pp, pp, vv, c1);
  FMA2(pp, pp, vv, c2);
  FMA2(pp, pp, vv, c3);
  FMA2(pp, pp, vv, c4);
  uint64_t zz;
  MUL2(zz, pp, xx);
  asm("mov.b64 {%0, %1}, %2;" : "=f"(za), "=f"(zb) : "l"(zz));
  if (va <= -7.2134752f) za = erfinv_tail(va) * xa;   // w >= 5 tail fixup
  if (vb <= -7.2134752f) zb = erfinv_tail(vb) * xb;
}

// ---------------- fully fused kernel: one block = one (b,c) row ----------------
// Phase 1: row sum/sumsq -> std (x row becomes L1-resident).
// Phase 2: 4 lone threads derive this row's shift / mask*scale constants.
// Phase 3: R14 hot body (8 elems/thread, both views).
__global__ void __launch_bounds__(512) fused_kernel(
    const float* __restrict__ x, float* __restrict__ out,
    uint4 kA, uint4 iA, uint4 kB, uint4 iB,
    uint4 kshA, uint4 kshB, uint4 kmask, uint4 kscale,
    uint32_t one) {
  int row = blockIdx.x;            // 0..8191
  int b   = row >> 6;
  size_t base = (size_t)row << 12;
  const float* xb = x + base;
  int tid = threadIdx.x;

  __shared__ float ss[16], qq[16];
  __shared__ float sm_sd, sm_ms0, sm_ms1;
  __shared__ int   sm_sh0, sm_sh1;

  // ---- phase 1: sum / sumsq over the 4096-elem row (coalesced float4) ----
  {
    const float4* xr = reinterpret_cast<const float4*>(xb);
    float s = 0.0f, q = 0.0f;
#pragma unroll
    for (int i = 0; i < 2; i++) {
      float4 v = xr[tid + (i << 9)];
      s += (v.x + v.y) + (v.z + v.w);
      q += (v.x * v.x + v.y * v.y) + (v.z * v.z + v.w * v.w);
    }
#pragma unroll
    for (int o = 16; o; o >>= 1) {
      s += __shfl_down_sync(0xFFFFFFFFu, s, o);
      q += __shfl_down_sync(0xFFFFFFFFu, q, o);
    }
    int w = tid >> 5;
    if ((tid & 31) == 0) { ss[w] = s; qq[w] = q; }
  }
  __syncthreads();

  // ---- phase 2: per-row constants (lone threads in distinct warps) ----
  if (tid == 0) {
    float S = 0.0f, Q = 0.0f;
#pragma unroll
    for (int i = 0; i < 16; i++) { S += ss[i]; Q += qq[i]; }
    float mean = S * (1.0f / 4096.0f);
    float var  = (Q - 4096.0f * mean * mean) * (1.0f / 4095.0f);
    sm_sd = 0.141421356237f * sqrtf(fmaxf(var, 0.0f));   // 0.1*sqrt(2)*std
  } else if (tid == 32) {
    // randint view 0: k1,k2 = split(k_shift); higher from k1, lower from k2
    uint32_t hb = xbits(kshA.x, kshA.y, (uint32_t)b);
    uint32_t lb = xbits(kshA.z, kshA.w, (uint32_t)b);
    sm_sh0 = -50 + (int)(((hb % 101u) * 68u + (lb % 101u)) % 101u);
  } else if (tid == 64) {
    uint32_t hb = xbits(kshB.x, kshB.y, (uint32_t)b);
    uint32_t lb = xbits(kshB.z, kshB.w, (uint32_t)b);
    sm_sh1 = -50 + (int)(((hb % 101u) * 68u + (lb % 101u)) % 101u);
  } else if (tid == 96) {
    float mk = (u01(xbits(kmask.x, kmask.y, (uint32_t)row)) > 0.1f) ? 1.0f : 0.0f;
    float u  = u01(xbits(kscale.x, kscale.y, (uint32_t)b));
    const float span = 1.2f - 0.8f;
    sm_ms0 = mk * fmaxf(0.8f, __fadd_rn(__fmul_rn(u, span), 0.8f));
  } else if (tid == 128) {
    float mk = (u01(xbits(kmask.z, kmask.w, (uint32_t)row)) > 0.1f) ? 1.0f : 0.0f;
    float u  = u01(xbits(kscale.z, kscale.w, (uint32_t)b));
    const float span = 1.2f - 0.8f;
    sm_ms1 = mk * fmaxf(0.8f, __fadd_rn(__fmul_rn(u, span), 0.8f));
  }
  __syncthreads();

  // ---- phase 3: hot body (identical to R14/R16) ----
  float sd  = sm_sd;
  float ms0 = sm_ms0;
  float ms1 = sm_ms1;
  unsigned s0 = (unsigned)tid * 8u;
  unsigned t0 = (unsigned)row * 4096u + s0;                // flat (b,c,s)
  unsigned u0 = (unsigned)(((int)s0 - sm_sh0) & 4095);     // rolled start, view 0
  unsigned u1 = (unsigned)(((int)s0 - sm_sh1) & 4095);     // rolled start, view 1

  uint32_t tka = t0 + kA.y;   // counter + k1, view 0
  uint32_t tkb = t0 + kB.y;   // counter + k1, view 1

#pragma unroll
  for (int g = 0; g < 2; g++) {                 // two float4 groups
    float4 o0, o1;
    float* p0 = &o0.x;
    float* p1 = &o1.x;
#pragma unroll
    for (int j = 0; j < 4; j++) {
      unsigned e = 4u * g + j;
      uint32_t wa = tf_xor(kA, iA, tka + e, one);
      uint32_t wb = tf_xor(kB, iB, tkb + e, one);
      float z0, z1;
      erfinv_pair(wa, wb, z0, z1);
      float xv0 = __ldg(xb + ((u0 + e) & 4095u));
      float xv1 = __ldg(xb + ((u1 + e) & 4095u));
      p0[j] = (xv0 + z0 * sd) * ms0;
      p1[j] = (xv1 + z1 * sd) * ms1;
    }
    *reinterpret_cast<float4*>(out + base + s0 + 4u * g)        = o0;
    *reinterpret_cast<float4*>(out + NTOT + base + s0 + 4u * g) = o1;
  }
}

// ---------------- host-side Threefry for constant key derivation ----------------
static inline uint32_t h_rotl(uint32_t x, int r) { return (x << r) | (x >> (32 - r)); }
static void h_tf(uint32_t k0, uint32_t k1, uint32_t x0, uint32_t x1,
                 uint32_t* o0, uint32_t* o1) {
  uint32_t k2 = k0 ^ k1 ^ 0x1BD11BDAu;
  x0 += k0; x1 += k1;
#define HR(r) { x0 += x1; x1 = h_rotl(x1, r); x1 ^= x0; }
  HR(13) HR(15) HR(26) HR(6)  x0 += k1; x1 += k2 + 1u;
  HR(17) HR(29) HR(16) HR(24) x0 += k2; x1 += k0 + 2u;
  HR(13) HR(15) HR(26) HR(6)  x0 += k0; x1 += k1 + 3u;
  HR(17) HR(29) HR(16) HR(24) x0 += k1; x1 += k2 + 4u;
  HR(13) HR(15) HR(26) HR(6)  x0 += k2; x1 += k0 + 5u;
#undef HR
  *o0 = x0; *o1 = x1;
}

extern "C" void kernel_launch(void* const* d_in, const int* in_sizes, int n_in,
                              void* d_out, int out_size) {
  const float* x = (const float*)d_in[0];
  float* out = (float*)d_out;

  uint32_t vk[2][2];
  h_tf(0u, 42u, 0u, 1u, &vk[0][0], &vk[0][1]);
  h_tf(0u, 42u, 0u, 2u, &vk[1][0], &vk[1][1]);

  uint4 kshA, kshB, kmask, kscale;
  uint32_t kn[2][2];   // noise keys per view
  for (int v = 0; v < 2; v++) {
    uint32_t kj[4][2];
    for (uint32_t j = 0; j < 4; j++)
      h_tf(vk[v][0], vk[v][1], 0u, j, &kj[j][0], &kj[j][1]);
    uint32_t s1[2], s2[2];
    h_tf(kj[0][0], kj[0][1], 0u, 0u, &s1[0], &s1[1]);
    h_tf(kj[0][0], kj[0][1], 0u, 1u, &s2[0], &s2[1]);
    kn[v][0] = kj[1][0]; kn[v][1] = kj[1][1];
    if (v == 0) {
      kshA.x = s1[0]; kshA.y = s1[1]; kshA.z = s2[0]; kshA.w = s2[1];
      kmask.x  = kj[2][0]; kmask.y  = kj[2][1];
      kscale.x = kj[3][0]; kscale.y = kj[3][1];
    } else {
      kshB.x = s1[0]; kshB.y = s1[1]; kshB.z = s2[0]; kshB.w = s2[1];
      kmask.z  = kj[2][0]; kmask.w  = kj[2][1];
      kscale.z = kj[3][0]; kscale.w = kj[3][1];
    }
  }

  // derived threefry constants, host-side
  uint4 kkv[2], iiv[2];
  for (int v = 0; v < 2; v++) {
    uint32_t k0 = kn[v][0], k1 = kn[v][1];
    uint32_t k2 = k0 ^ k1 ^ 0x1BD11BDAu;
    kkv[v].x = k0;      kkv[v].y = k1;      kkv[v].z = k2;      kkv[v].w = k2 + 1u;
    iiv[v].x = k0 + 2u; iiv[v].y = k1 + 3u; iiv[v].z = k2 + 4u; iiv[v].w = k0 + 5u;
  }

  fused_kernel<<<NROW, 512>>>(x, out, kkv[0], iiv[0], kkv[1], iiv[1],
                              kshA, kshB, kmask, kscale, 1u);
}